// round 6
// baseline (speedup 1.0000x reference)
#include <cuda_runtime.h>
#include <cstdint>

// ---------------------------------------------------------------------------
// QuantLinear, sm_100 base ISA. tf32 mma.sync.m16n8k8.
//   out[M,T] = x[M,K] @ W[K,T] + bias,  W[k,t]=s[k/128,t]*(q[k,t]-z[k/128,t])
//   M=4096, K=4096, T=11008.
// CTA tile 128x256, 256 threads, 8 warps of 64x64 (2m x 4n).
// A: cp.async double-buffer, row-major stride 36 (conflict-free frags).
// B: fused dequant, col-major stride 36, double-buffer; 1 column/thread,
//    8x STS.128 per stage; qweight LDG issued one stage ahead (latency hidden
//    under the MMA block). R1-proven pipeline skeleton: one commit_group +
//    wait_group 0 + __syncthreads per stage.
// ---------------------------------------------------------------------------

#define NTHREADS 256
#define BM 128
#define BN 256
#define BK 32
#define AST 36                  // A row stride (floats)
#define BST 36                  // B col stride (floats)
#define A_BUF (BM * AST)        // 4608 floats / stage
#define B_BUF (BN * BST)        // 9216 floats / stage
#define SMEM_FLOATS (2 * A_BUF + 2 * B_BUF)
#define SMEM_BYTES  (SMEM_FLOATS * 4)   // 110592

__device__ __forceinline__ uint32_t f2tf32(float x) {
    uint32_t r;
    asm("cvt.rna.tf32.f32 %0, %1;" : "=r"(r) : "f"(x));
    return r;
}
__device__ __forceinline__ void cp_async16(uint32_t saddr, const void* g) {
    asm volatile("cp.async.cg.shared.global [%0], [%1], 16;" :: "r"(saddr), "l"(g));
}
__device__ __forceinline__ void mma_tf32(float c[4], const uint32_t a[4], const uint32_t b[2]) {
    asm volatile(
        "mma.sync.aligned.m16n8k8.row.col.f32.tf32.tf32.f32 "
        "{%0,%1,%2,%3}, {%4,%5,%6,%7}, {%8,%9}, {%0,%1,%2,%3};"
        : "+f"(c[0]), "+f"(c[1]), "+f"(c[2]), "+f"(c[3])
        : "r"(a[0]), "r"(a[1]), "r"(a[2]), "r"(a[3]), "r"(b[0]), "r"(b[1]));
}

__global__ void __launch_bounds__(NTHREADS)
qgemm_w64_kernel(const float* __restrict__ x,
                 const int*   __restrict__ qw,
                 const float* __restrict__ scales,
                 const float* __restrict__ zeros,
                 const float* __restrict__ bias,
                 float*       __restrict__ out,
                 int M, int K, int T)
{
    extern __shared__ float smem[];
    float* As = smem;                  // 2 x [128 rows][AST]
    float* Bs = smem + 2 * A_BUF;      // 2 x [256 cols][BST]  (col-major)

    const int tid  = threadIdx.x;
    const int warp = tid >> 5;
    const int lane = tid & 31;
    const int g    = lane >> 2;        // 0..7
    const int q    = lane & 3;         // 0..3
    const int wm   = (warp & 1) * 64;  // 2 m-bands
    const int wn   = (warp >> 1) * 64; // 4 n-bands
    const int m0   = blockIdx.y * BM;
    const int n0   = blockIdx.x * BN;
    const int NS   = K / BK;           // 128

    const int gcol = n0 + tid;         // this thread's dequant column (1 of 256)

    float acc[4][8][4];
    #pragma unroll
    for (int mf = 0; mf < 4; ++mf)
        #pragma unroll
        for (int nf = 0; nf < 8; ++nf)
            #pragma unroll
            for (int i = 0; i < 4; ++i) acc[mf][nf][i] = 0.0f;

    // ---- helpers ----
    auto cpa_stage = [&](int buf, int s) {
        uint32_t sbase = (uint32_t)__cvta_generic_to_shared(As + buf * A_BUF);
        const float* xg = x + (size_t)m0 * K + s * BK;
        #pragma unroll
        for (int i = 0; i < 4; ++i) {
            int ch  = tid + i * NTHREADS;      // 0..1023
            int row = ch >> 3, j = ch & 7;
            cp_async16(sbase + (uint32_t)(row * AST + 4 * j) * 4u,
                       xg + (size_t)row * K + 4 * j);
        }
        asm volatile("cp.async.commit_group;");
    };

    int   wqn[4];                      // packed weights for the pending stage
    float sc, nz, sp, zp;

    auto ldg_w = [&](int s) {
        const int rb = s * 4;
        #pragma unroll
        for (int r = 0; r < 4; ++r)
            wqn[r] = __ldg(&qw[(size_t)(rb + r) * T + gcol]);
    };

    auto dequant_to = [&](int buf) {
        float* Bp = Bs + buf * B_BUF + tid * BST;
        #pragma unroll
        for (int r = 0; r < 4; ++r) {
            const uint32_t w = (uint32_t)wqn[r];
            uint32_t u[8];
            #pragma unroll
            for (int i = 0; i < 8; ++i) {
                float qf = __uint_as_float(0x4B000000u | ((w >> (4 * i)) & 0xFu))
                           - 8388608.0f;       // exact small int
                u[i] = f2tf32(fmaf(qf, sc, nz));
            }
            uint32_t a0 = (uint32_t)__cvta_generic_to_shared(Bp + 8 * r);
            asm volatile("st.shared.v4.b32 [%0], {%1,%2,%3,%4};"
                         :: "r"(a0), "r"(u[0]), "r"(u[1]), "r"(u[2]), "r"(u[3]));
            asm volatile("st.shared.v4.b32 [%0], {%1,%2,%3,%4};"
                         :: "r"(a0 + 16), "r"(u[4]), "r"(u[5]), "r"(u[6]), "r"(u[7]));
        }
    };

    // ---- prologue: stage 0 ----
    ldg_w(0);
    sc = __ldg(&scales[gcol]);
    nz = -sc * __ldg(&zeros[gcol]);
    cpa_stage(0, 0);
    dequant_to(0);
    asm volatile("cp.async.wait_group 0;");
    __syncthreads();

    // ---- main loop ----
    for (int s = 0; s < NS; ++s) {
        // prefetch stage s+1: A via cp.async, weights via LDG (hidden by MMA)
        if (s + 1 < NS) {
            cpa_stage((s + 1) & 1, s + 1);
            ldg_w(s + 1);
            if (((s + 1) & 3) == 0) {          // next stage starts a new group
                const int gn = (s + 1) >> 2;
                sp = __ldg(&scales[(size_t)gn * T + gcol]);
                zp = __ldg(&zeros [(size_t)gn * T + gcol]);
            }
        }

        // compute stage s
        {
            const float*    Ab = As + (s & 1) * A_BUF;
            const uint32_t* Bb = (const uint32_t*)(Bs + (s & 1) * B_BUF);
            #pragma unroll
            for (int kk = 0; kk < 4; ++kk) {
                const int kb = kk * 8;
                uint32_t bfrag[8][2];
                #pragma unroll
                for (int nf = 0; nf < 8; ++nf) {
                    const int n = wn + nf * 8 + g;
                    bfrag[nf][0] = Bb[n * BST + kb + q];
                    bfrag[nf][1] = Bb[n * BST + kb + 4 + q];
                }
                uint32_t afrag[4][4];
                #pragma unroll
                for (int mf = 0; mf < 4; ++mf) {
                    const int r0 = wm + mf * 16 + g;
                    afrag[mf][0] = f2tf32(Ab[(r0)     * AST + kb + q]);
                    afrag[mf][1] = f2tf32(Ab[(r0 + 8) * AST + kb + q]);
                    afrag[mf][2] = f2tf32(Ab[(r0)     * AST + kb + q + 4]);
                    afrag[mf][3] = f2tf32(Ab[(r0 + 8) * AST + kb + q + 4]);
                }
                #pragma unroll
                for (int mf = 0; mf < 4; ++mf)
                    #pragma unroll
                    for (int nf = 0; nf < 8; ++nf)
                        mma_tf32(acc[mf][nf], afrag[mf], bfrag[nf]);
            }
        }

        // produce B for stage s+1 (weights LDG'd at loop top, latency hidden)
        if (s + 1 < NS) {
            if (((s + 1) & 3) == 0) { sc = sp; nz = -sp * zp; }
            dequant_to((s + 1) & 1);
            asm volatile("cp.async.wait_group 0;");
        }
        __syncthreads();
    }

    // ---- epilogue ----
    #pragma unroll
    for (int nf = 0; nf < 8; ++nf) {
        const int col = n0 + wn + nf * 8 + 2 * q;
        const float bx = __ldg(&bias[col]);
        const float by = __ldg(&bias[col + 1]);
        #pragma unroll
        for (int mf = 0; mf < 4; ++mf) {
            const int row = m0 + wm + mf * 16 + g;
            float2 v0, v1;
            v0.x = acc[mf][nf][0] + bx;  v0.y = acc[mf][nf][1] + by;
            v1.x = acc[mf][nf][2] + bx;  v1.y = acc[mf][nf][3] + by;
            *(float2*)&out[(size_t)row * T + col]       = v0;
            *(float2*)&out[(size_t)(row + 8) * T + col] = v1;
        }
    }
}

extern "C" void kernel_launch(void* const* d_in, const int* in_sizes, int n_in,
                              void* d_out, int out_size)
{
    const float* x      = (const float*)d_in[0];
    const int*   qw     = (const int*)  d_in[1];
    const float* scales = (const float*)d_in[2];
    const float* zeros  = (const float*)d_in[3];
    const float* bias   = (const float*)d_in[4];
    float*       out    = (float*)d_out;

    const int T = in_sizes[4];               // 11008
    const int K = (in_sizes[1] / T) * 8;     // 4096
    const int M = in_sizes[0] / K;           // 4096

    cudaFuncSetAttribute(qgemm_w64_kernel,
                         cudaFuncAttributeMaxDynamicSharedMemorySize, SMEM_BYTES);

    dim3 grid(T / BN, M / BM);               // 43 x 32
    qgemm_w64_kernel<<<grid, NTHREADS, SMEM_BYTES>>>(x, qw, scales, zeros, bias, out,
                                                     M, K, T);
}

// round 8
// speedup vs baseline: 1.4059x; 1.4059x over previous
#include <cuda_runtime.h>
#include <cstdint>

// ---------------------------------------------------------------------------
// QuantLinear via dual-int8 IMMA (m16n8k32.s8.u8), exact decomposition.
//   x ~= S_b*(x0 + x1/254), x0,x1 int8;  W[k,t] = s*(q - z), q in 0..15 (u8)
//   out = sum_g s_g*S_b*[ (P0 - z*X0) + (P1 - z*X1)/254 ] + bias
//   P_c = sum_{k in g} xc*q (int32, exact),  X_c = sum_{k in g} xc.
// Kernel 1: quantize x -> k-permuted packed int8 matching qweight nibble order
//           (word w' = kq*2+half so A frags load as LDS.64).
// Kernel 2: GEMM, 256 thr (R6-proven skeleton), CTA 128x128, warp 32x64,
//           K-stage 128 (= group), double-buffered cp.async, B stays packed.
// ---------------------------------------------------------------------------

#define MDIM 4096
#define KDIM 4096
#define NSG  32                  // 32 k-stages of 128
#define NTH  256

__device__ uint32_t g_xp0[MDIM * 1024];     // permuted packed x0
__device__ uint32_t g_xp1[MDIM * 1024];     // permuted packed x1
__device__ float    g_XT0[NSG * MDIM];      // group sums of x0, [g][b]
__device__ float    g_XT1[NSG * MDIM];
__device__ float    g_S[MDIM];              // per-row scale

// ---------------- kernel 1: quantize + permute-pack ----------------
__global__ void __launch_bounds__(128)
quant_kernel(const float* __restrict__ x) {
    __shared__ float red[128];
    __shared__ int   ss0[128], ss1[128];
    const int b = blockIdx.x, tid = threadIdx.x;
    const float* xr = x + (size_t)b * KDIM + tid * 32;

    float v[32]; float mx = 0.f;
    #pragma unroll
    for (int i = 0; i < 32; ++i) { v[i] = xr[i]; mx = fmaxf(mx, fabsf(v[i])); }
    red[tid] = mx; __syncthreads();
    for (int o = 64; o > 0; o >>= 1) {
        if (tid < o) red[tid] = fmaxf(red[tid], red[tid + o]);
        __syncthreads();
    }
    const float S    = fmaxf(red[0], 1e-20f) * (1.f / 127.f);
    const float invS = 1.f / S;

    int q0[32], q1[32]; int s0 = 0, s1 = 0;
    #pragma unroll
    for (int i = 0; i < 32; ++i) {
        int a = __float2int_rn(v[i] * invS);
        a = max(-127, min(127, a));
        float r = v[i] - S * (float)a;
        int c = __float2int_rn(r * (254.f * invS));
        c = max(-127, min(127, c));
        q0[i] = a; q1[i] = c; s0 += a; s1 += c;
    }
    // word w' = kq*2 + half; byte j <- local k = (kq>>1)*8 + (kq&1) + 2j + 16*half
    const uint32_t base = (uint32_t)b * 1024u + tid * 8u;
    #pragma unroll
    for (int w = 0; w < 8; ++w) {
        const int kq = w >> 1, half = w & 1;
        const int k0 = (kq >> 1) * 8 + (kq & 1) + 16 * half;
        uint32_t u0 = 0, u1 = 0;
        #pragma unroll
        for (int j = 0; j < 4; ++j) {
            u0 |= (uint32_t)(q0[k0 + 2 * j] & 255) << (8 * j);
            u1 |= (uint32_t)(q1[k0 + 2 * j] & 255) << (8 * j);
        }
        g_xp0[base + w] = u0; g_xp1[base + w] = u1;
    }
    ss0[tid] = s0; ss1[tid] = s1; __syncthreads();
    if (tid < 32) {
        int X0 = ss0[4 * tid] + ss0[4 * tid + 1] + ss0[4 * tid + 2] + ss0[4 * tid + 3];
        int X1 = ss1[4 * tid] + ss1[4 * tid + 1] + ss1[4 * tid + 2] + ss1[4 * tid + 3];
        g_XT0[tid * MDIM + b] = (float)X0;
        g_XT1[tid * MDIM + b] = (float)X1;
    }
    if (tid == 0) g_S[b] = S;
}

// ---------------- kernel 2: GEMM ----------------
// SMEM (bytes): A [buf2][comp2][128 rows][40 words] row stride 160B
#define A_CSZ  20480
#define A_BSZ  (2 * A_CSZ)                 // 40960
#define OFF_B  (2 * A_BSZ)                 // 81920
#define B_RST  544
#define B_SZ   (16 * B_RST)                // 8704
#define OFF_V  (OFF_B + 2 * B_SZ)          // 99328: [buf] s|z|X0|X1 (128 f each)
#define V_SZ   2048
#define OFF_SB (OFF_V + 2 * V_SZ)          // 103424: S[128] bias[128]
#define SMEMB  (OFF_SB + 1024)             // 104448

__device__ __forceinline__ void cp_async16(uint32_t saddr, const void* g) {
    asm volatile("cp.async.cg.shared.global [%0], [%1], 16;" :: "r"(saddr), "l"(g));
}
__device__ __forceinline__ void imma_su(int c[4], uint32_t a0, uint32_t a1,
                                        uint32_t a2, uint32_t a3,
                                        uint32_t b0, uint32_t b1) {
    asm volatile(
        "mma.sync.aligned.m16n8k32.row.col.s32.s8.u8.s32 "
        "{%0,%1,%2,%3}, {%4,%5,%6,%7}, {%8,%9}, {%0,%1,%2,%3};"
        : "+r"(c[0]), "+r"(c[1]), "+r"(c[2]), "+r"(c[3])
        : "r"(a0), "r"(a1), "r"(a2), "r"(a3), "r"(b0), "r"(b1));
}

__global__ void __launch_bounds__(NTH)
qgemm_i8_kernel(const int*   __restrict__ qw,
                const float* __restrict__ scales,
                const float* __restrict__ zeros,
                const float* __restrict__ bias,
                float*       __restrict__ out,
                int T)
{
    extern __shared__ char smem[];
    const uint32_t sb = (uint32_t)__cvta_generic_to_shared(smem);
    float* smf = (float*)smem;

    const int tid  = threadIdx.x;
    const int warp = tid >> 5;
    const int lane = tid & 31;
    const int r4   = lane >> 2;           // 0..7
    const int kq   = lane & 3;            // 0..3
    const uint32_t sh = (kq & 1) * 4;     // nibble shift
    const int wm   = (warp >> 1) * 32;    // 4 m-bands
    const int wn   = (warp & 1) * 64;     // 2 n-bands
    const int m0   = blockIdx.y * 128;
    const int n0   = blockIdx.x * 128;

    auto load_stage = [&](int s, int buf) {
        // A: 2 comps x 128 rows x 8 16B-chunks = 2048 -> 8/thread
        #pragma unroll
        for (int i = 0; i < 8; ++i) {
            int idx  = tid + i * NTH;
            int comp = idx >> 10, rem = idx & 1023;
            int row  = rem >> 3,  j   = rem & 7;
            const uint32_t* src = (comp ? g_xp1 : g_xp0);
            cp_async16(sb + buf * A_BSZ + comp * A_CSZ + row * 160 + j * 16,
                       src + (size_t)(m0 + row) * 1024 + 32 * s + 4 * j);
        }
        // B: 16 word-rows x 128 cols -> 512 chunks -> 2/thread
        #pragma unroll
        for (int i = 0; i < 2; ++i) {
            int idx = tid + i * NTH;
            int wr = idx >> 5, cq = (idx & 31) * 4;
            cp_async16(sb + OFF_B + buf * B_SZ + wr * B_RST + cq * 4,
                       qw + (size_t)(16 * s + wr) * T + n0 + cq);
        }
        // vectors s|z|X0|X1
        if (tid < 128) {
            int a = tid >> 5, o = (tid & 31) * 4;
            const float* src;
            if      (a == 0) src = scales + (size_t)s * T + n0 + o;
            else if (a == 1) src = zeros  + (size_t)s * T + n0 + o;
            else if (a == 2) src = g_XT0 + (size_t)s * MDIM + m0 + o;
            else             src = g_XT1 + (size_t)s * MDIM + m0 + o;
            cp_async16(sb + OFF_V + buf * V_SZ + a * 512 + o * 4, src);
        }
        asm volatile("cp.async.commit_group;");
    };

    // ---- prologue ----
    load_stage(0, 0);
    if (tid < 128)       smf[OFF_SB / 4 + tid] = g_S[m0 + tid];
    else                 smf[OFF_SB / 4 + tid] = bias[n0 + (tid - 128)];
    asm volatile("cp.async.wait_group 0;");
    __syncthreads();

    float Sr[2][2];
    #pragma unroll
    for (int mt = 0; mt < 2; ++mt)
        #pragma unroll
        for (int h = 0; h < 2; ++h)
            Sr[mt][h] = smf[OFF_SB / 4 + wm + mt * 16 + r4 + 8 * h];

    float F[2][8][4];
    #pragma unroll
    for (int mt = 0; mt < 2; ++mt)
        #pragma unroll
        for (int nt = 0; nt < 8; ++nt)
            #pragma unroll
            for (int i = 0; i < 4; ++i) F[mt][nt][i] = 0.f;

    int buf = 0;
    for (int s = 0; s < NSG; ++s) {
        if (s + 1 < NSG) load_stage(s + 1, buf ^ 1);

        const uint32_t baseA = sb + buf * A_BSZ;
        const uint32_t baseB = sb + OFF_B + buf * B_SZ;
        const int vf = OFF_V / 4 + buf * (V_SZ / 4);

        #pragma unroll
        for (int half = 0; half < 2; ++half) {
            int P[2][2][4][4];
            #pragma unroll
            for (int c2 = 0; c2 < 2; ++c2)
                #pragma unroll
                for (int mt = 0; mt < 2; ++mt)
                    #pragma unroll
                    for (int nt = 0; nt < 4; ++nt)
                        #pragma unroll
                        for (int i = 0; i < 4; ++i) P[c2][mt][nt][i] = 0;

            #pragma unroll
            for (int kk = 0; kk < 4; ++kk) {
                // B: load packed words once, extract u8 nibbles (shared by comps)
                uint32_t b0[4], b1[4];
                #pragma unroll
                for (int nt = 0; nt < 4; ++nt) {
                    const int col = wn + (half * 4 + nt) * 8 + r4;
                    const uint32_t wrd = baseB + (kk * 4 + (kq >> 1)) * B_RST + col * 4;
                    uint32_t rw0, rw1;
                    asm volatile("ld.shared.b32 %0, [%1];" : "=r"(rw0) : "r"(wrd));
                    asm volatile("ld.shared.b32 %0, [%1];" : "=r"(rw1) : "r"(wrd + 2 * B_RST));
                    b0[nt] = (rw0 >> sh) & 0x0F0F0F0Fu;
                    b1[nt] = (rw1 >> sh) & 0x0F0F0F0Fu;
                }
                #pragma unroll
                for (int comp = 0; comp < 2; ++comp) {
                    uint32_t a[2][4];
                    #pragma unroll
                    for (int mt = 0; mt < 2; ++mt) {
                        const uint32_t rowb = baseA + comp * A_CSZ +
                            (uint32_t)(wm + mt * 16 + r4) * 160 + kk * 32 + kq * 8;
                        asm volatile("ld.shared.v2.b32 {%0,%1}, [%2];"
                                     : "=r"(a[mt][0]), "=r"(a[mt][2]) : "r"(rowb));
                        asm volatile("ld.shared.v2.b32 {%0,%1}, [%2];"
                                     : "=r"(a[mt][1]), "=r"(a[mt][3]) : "r"(rowb + 8 * 160));
                    }
                    #pragma unroll
                    for (int nt = 0; nt < 4; ++nt) {
                        imma_su(P[comp][0][nt], a[0][0], a[0][1], a[0][2], a[0][3],
                                b0[nt], b1[nt]);
                        imma_su(P[comp][1][nt], a[1][0], a[1][1], a[1][2], a[1][3],
                                b0[nt], b1[nt]);
                    }
                }
            }

            // fold this nt-half into F (per group: F += s*Sr*wgt*(P - z*X))
            #pragma unroll
            for (int comp = 0; comp < 2; ++comp) {
                const float wgt = comp ? (1.f / 254.f) : 1.f;
                float Xr[2][2];
                #pragma unroll
                for (int mt = 0; mt < 2; ++mt)
                    #pragma unroll
                    for (int h = 0; h < 2; ++h)
                        Xr[mt][h] = smf[vf + (2 + comp) * 128 + wm + mt * 16 + r4 + 8 * h];
                #pragma unroll
                for (int nt = 0; nt < 4; ++nt) {
                    #pragma unroll
                    for (int c = 0; c < 2; ++c) {
                        const int cl = wn + (half * 4 + nt) * 8 + 2 * kq + c;
                        const float sv = smf[vf + cl] * wgt;
                        const float zv = smf[vf + 128 + cl];
                        #pragma unroll
                        for (int mt = 0; mt < 2; ++mt)
                            #pragma unroll
                            for (int h = 0; h < 2; ++h) {
                                const int i = 2 * h + c;
                                float t = fmaf(-zv, Xr[mt][h],
                                               (float)P[comp][mt][nt][i]);
                                F[mt][half * 4 + nt][i] =
                                    fmaf(sv * Sr[mt][h], t, F[mt][half * 4 + nt][i]);
                            }
                    }
                }
            }
        }

        if (s + 1 < NSG) asm volatile("cp.async.wait_group 0;");
        __syncthreads();
        buf ^= 1;
    }

    // ---- output ----
    #pragma unroll
    for (int mt = 0; mt < 2; ++mt)
        #pragma unroll
        for (int nt = 0; nt < 8; ++nt)
            #pragma unroll
            for (int h = 0; h < 2; ++h) {
                const int row = m0 + wm + mt * 16 + r4 + 8 * h;
                const int cl  = wn + nt * 8 + 2 * kq;
                float2 v;
                v.x = F[mt][nt][2 * h + 0] + smf[OFF_SB / 4 + 128 + cl];
                v.y = F[mt][nt][2 * h + 1] + smf[OFF_SB / 4 + 128 + cl + 1];
                *(float2*)&out[(size_t)row * T + n0 + cl] = v;
            }
}

extern "C" void kernel_launch(void* const* d_in, const int* in_sizes, int n_in,
                              void* d_out, int out_size)
{
    const float* x      = (const float*)d_in[0];
    const int*   qw     = (const int*)  d_in[1];
    const float* scales = (const float*)d_in[2];
    const float* zeros  = (const float*)d_in[3];
    const float* bias   = (const float*)d_in[4];
    float*       out    = (float*)d_out;

    const int T = in_sizes[4];               // 11008

    quant_kernel<<<MDIM, 128>>>(x);

    cudaFuncSetAttribute(qgemm_i8_kernel,
                         cudaFuncAttributeMaxDynamicSharedMemorySize, SMEMB);
    dim3 grid(T / 128, MDIM / 128);          // 86 x 32
    qgemm_i8_kernel<<<grid, NTH, SMEMB>>>(qw, scales, zeros, bias, out, T);
}

// round 9
// speedup vs baseline: 1.7830x; 1.2682x over previous
#include <cuda_runtime.h>
#include <cstdint>

// ---------------------------------------------------------------------------
// QuantLinear via dual-int8 IMMA (m16n8k32.s8.u8), exact decomposition.
//   x ~= S_b*(x0 + x1/254);  P = 254*P0 + P1 (exact int32, single accumulator)
//   out = Sr * sum_g (s_g/254)*(P_g - z_g*Xtot_g) + bias,  Xtot = 254*X0+X1
// Kernel 1: quantize x -> k-permuted packed int8 (matches qweight nibbles).
// Kernel 2: 512 thr, 16 warps of 32x32, CTA 128x128, K-stage 128 (= group),
//           double-buffered cp.async; comp0 IMMAs -> P*=254 -> comp1 IMMAs.
// ---------------------------------------------------------------------------

#define MDIM 4096
#define KDIM 4096
#define NSG  32
#define NTH  512

__device__ uint32_t g_xp0[MDIM * 1024];
__device__ uint32_t g_xp1[MDIM * 1024];
__device__ float    g_XT[NSG * MDIM];       // 254*X0+X1 per [g][b], exact fp32
__device__ float    g_S[MDIM];

// ---------------- kernel 1: quantize + permute-pack ----------------
__global__ void __launch_bounds__(128)
quant_kernel(const float* __restrict__ x) {
    __shared__ float red[128];
    __shared__ int   ss0[128], ss1[128];
    const int b = blockIdx.x, tid = threadIdx.x;
    const float* xr = x + (size_t)b * KDIM + tid * 32;

    float v[32]; float mx = 0.f;
    #pragma unroll
    for (int i = 0; i < 32; ++i) { v[i] = xr[i]; mx = fmaxf(mx, fabsf(v[i])); }
    red[tid] = mx; __syncthreads();
    for (int o = 64; o > 0; o >>= 1) {
        if (tid < o) red[tid] = fmaxf(red[tid], red[tid + o]);
        __syncthreads();
    }
    const float S    = fmaxf(red[0], 1e-20f) * (1.f / 127.f);
    const float invS = 1.f / S;

    int q0[32], q1[32]; int s0 = 0, s1 = 0;
    #pragma unroll
    for (int i = 0; i < 32; ++i) {
        int a = __float2int_rn(v[i] * invS);
        a = max(-127, min(127, a));
        float r = v[i] - S * (float)a;
        int c = __float2int_rn(r * (254.f * invS));
        c = max(-127, min(127, c));
        q0[i] = a; q1[i] = c; s0 += a; s1 += c;
    }
    // word w' = kq*2 + half; byte j <- local k = (kq>>1)*8 + (kq&1) + 2j + 16*half
    const uint32_t base = (uint32_t)b * 1024u + tid * 8u;
    #pragma unroll
    for (int w = 0; w < 8; ++w) {
        const int kq = w >> 1, half = w & 1;
        const int k0 = (kq >> 1) * 8 + (kq & 1) + 16 * half;
        uint32_t u0 = 0, u1 = 0;
        #pragma unroll
        for (int j = 0; j < 4; ++j) {
            u0 |= (uint32_t)(q0[k0 + 2 * j] & 255) << (8 * j);
            u1 |= (uint32_t)(q1[k0 + 2 * j] & 255) << (8 * j);
        }
        g_xp0[base + w] = u0; g_xp1[base + w] = u1;
    }
    ss0[tid] = s0; ss1[tid] = s1; __syncthreads();
    if (tid < 32) {
        int X0 = ss0[4 * tid] + ss0[4 * tid + 1] + ss0[4 * tid + 2] + ss0[4 * tid + 3];
        int X1 = ss1[4 * tid] + ss1[4 * tid + 1] + ss1[4 * tid + 2] + ss1[4 * tid + 3];
        g_XT[tid * MDIM + b] = (float)(254 * X0 + X1);
    }
    if (tid == 0) g_S[b] = S;
}

// ---------------- kernel 2: GEMM ----------------
#define A_CSZ  20480                       // 128 rows x 160B (40-word stride)
#define A_BSZ  (2 * A_CSZ)                 // per buf (2 comps)
#define OFF_B  (2 * A_BSZ)                 // 81920
#define B_RST  544
#define B_SZ   (16 * B_RST)                // 8704
#define OFF_V  (OFF_B + 2 * B_SZ)          // 99328: [buf] s|z|Xt (128 f each)
#define V_SZ   1536
#define OFF_SB (OFF_V + 2 * V_SZ)          // 102400: S[128] bias[128]
#define SMEMB  (OFF_SB + 1024)             // 103424

__device__ __forceinline__ void cp_async16(uint32_t saddr, const void* g) {
    asm volatile("cp.async.cg.shared.global [%0], [%1], 16;" :: "r"(saddr), "l"(g));
}
__device__ __forceinline__ void imma_su(int c[4], uint32_t a0, uint32_t a1,
                                        uint32_t a2, uint32_t a3,
                                        uint32_t b0, uint32_t b1) {
    asm volatile(
        "mma.sync.aligned.m16n8k32.row.col.s32.s8.u8.s32 "
        "{%0,%1,%2,%3}, {%4,%5,%6,%7}, {%8,%9}, {%0,%1,%2,%3};"
        : "+r"(c[0]), "+r"(c[1]), "+r"(c[2]), "+r"(c[3])
        : "r"(a0), "r"(a1), "r"(a2), "r"(a3), "r"(b0), "r"(b1));
}

__global__ void __launch_bounds__(NTH)
qgemm_i8_kernel(const int*   __restrict__ qw,
                const float* __restrict__ scales,
                const float* __restrict__ zeros,
                const float* __restrict__ bias,
                float*       __restrict__ out,
                int T)
{
    extern __shared__ char smem[];
    const uint32_t sb = (uint32_t)__cvta_generic_to_shared(smem);
    float* smf = (float*)smem;

    const int tid  = threadIdx.x;
    const int warp = tid >> 5;
    const int lane = tid & 31;
    const int r4   = lane >> 2;
    const int kq   = lane & 3;
    const uint32_t sh = (kq & 1) * 4;
    const int wm   = (warp >> 2) * 32;    // 4 m-bands
    const int wn   = (warp & 3) * 32;     // 4 n-bands
    const int m0   = blockIdx.y * 128;
    const int n0   = blockIdx.x * 128;

    auto load_stage = [&](int s, int buf) {
        #pragma unroll
        for (int i = 0; i < 4; ++i) {              // A: 2048 chunks
            int idx  = tid + i * NTH;
            int comp = idx >> 10, rem = idx & 1023;
            int row  = rem >> 3,  j   = rem & 7;
            const uint32_t* src = (comp ? g_xp1 : g_xp0);
            cp_async16(sb + buf * A_BSZ + comp * A_CSZ + row * 160 + j * 16,
                       src + (size_t)(m0 + row) * 1024 + 32 * s + 4 * j);
        }
        {                                          // B: 512 chunks, 1/thread
            int wr = tid >> 5, cq = (tid & 31) * 4;
            cp_async16(sb + OFF_B + buf * B_SZ + wr * B_RST + cq * 4,
                       qw + (size_t)(16 * s + wr) * T + n0 + cq);
        }
        if (tid < 96) {                            // vectors s|z|Xt
            int a = tid >> 5, o = (tid & 31) * 4;
            const float* src;
            if      (a == 0) src = scales + (size_t)s * T + n0 + o;
            else if (a == 1) src = zeros  + (size_t)s * T + n0 + o;
            else             src = g_XT  + (size_t)s * MDIM + m0 + o;
            cp_async16(sb + OFF_V + buf * V_SZ + a * 512 + o * 4, src);
        }
        asm volatile("cp.async.commit_group;");
    };

    // ---- prologue ----
    load_stage(0, 0);
    if (tid < 128)       smf[OFF_SB / 4 + tid] = g_S[m0 + tid];
    else if (tid < 256)  smf[OFF_SB / 4 + tid] = bias[n0 + (tid - 128)];
    asm volatile("cp.async.wait_group 0;");
    __syncthreads();

    float F[2][4][4];
    #pragma unroll
    for (int mt = 0; mt < 2; ++mt)
        #pragma unroll
        for (int nt = 0; nt < 4; ++nt)
            #pragma unroll
            for (int i = 0; i < 4; ++i) F[mt][nt][i] = 0.f;

    int buf = 0;
    for (int s = 0; s < NSG; ++s) {
        if (s + 1 < NSG) load_stage(s + 1, buf ^ 1);

        const uint32_t baseB = sb + OFF_B + buf * B_SZ;
        const int vf = OFF_V / 4 + buf * (V_SZ / 4);

        int P[2][4][4];
        #pragma unroll
        for (int mt = 0; mt < 2; ++mt)
            #pragma unroll
            for (int nt = 0; nt < 4; ++nt)
                #pragma unroll
                for (int i = 0; i < 4; ++i) P[mt][nt][i] = 0;

        #pragma unroll
        for (int comp = 0; comp < 2; ++comp) {
            const uint32_t baseA = sb + buf * A_BSZ + comp * A_CSZ;
            if (comp == 1) {             // P = 254*P0, then comp1 accumulates
                #pragma unroll
                for (int mt = 0; mt < 2; ++mt)
                    #pragma unroll
                    for (int nt = 0; nt < 4; ++nt)
                        #pragma unroll
                        for (int i = 0; i < 4; ++i) P[mt][nt][i] *= 254;
            }
            #pragma unroll
            for (int kk = 0; kk < 4; ++kk) {
                uint32_t a[2][4];
                #pragma unroll
                for (int mt = 0; mt < 2; ++mt) {
                    const uint32_t rowb = baseA +
                        (uint32_t)(wm + mt * 16 + r4) * 160 + kk * 32 + kq * 8;
                    asm volatile("ld.shared.v2.b32 {%0,%1}, [%2];"
                                 : "=r"(a[mt][0]), "=r"(a[mt][2]) : "r"(rowb));
                    asm volatile("ld.shared.v2.b32 {%0,%1}, [%2];"
                                 : "=r"(a[mt][1]), "=r"(a[mt][3]) : "r"(rowb + 8 * 160));
                }
                #pragma unroll
                for (int nt = 0; nt < 4; ++nt) {
                    const int col = wn + nt * 8 + r4;
                    const uint32_t wrd = baseB + (kk * 4 + (kq >> 1)) * B_RST + col * 4;
                    uint32_t rw0, rw1;
                    asm volatile("ld.shared.b32 %0, [%1];" : "=r"(rw0) : "r"(wrd));
                    asm volatile("ld.shared.b32 %0, [%1];" : "=r"(rw1) : "r"(wrd + 2 * B_RST));
                    const uint32_t b0 = (rw0 >> sh) & 0x0F0F0F0Fu;
                    const uint32_t b1 = (rw1 >> sh) & 0x0F0F0F0Fu;
                    imma_su(P[0][nt], a[0][0], a[0][1], a[0][2], a[0][3], b0, b1);
                    imma_su(P[1][nt], a[1][0], a[1][1], a[1][2], a[1][3], b0, b1);
                }
            }
        }

        // ---- per-group fold: F += (s/254)*(P - z*Xtot) ----
        {
            float Xr[2][2];
            #pragma unroll
            for (int mt = 0; mt < 2; ++mt)
                #pragma unroll
                for (int h = 0; h < 2; ++h)
                    Xr[mt][h] = smf[vf + 256 + wm + mt * 16 + r4 + 8 * h];
            #pragma unroll
            for (int nt = 0; nt < 4; ++nt) {
                #pragma unroll
                for (int c = 0; c < 2; ++c) {
                    const int cl = wn + nt * 8 + 2 * kq + c;
                    const float sv254 = smf[vf + cl] * (1.f / 254.f);
                    const float zv    = smf[vf + 128 + cl];
                    #pragma unroll
                    for (int mt = 0; mt < 2; ++mt)
                        #pragma unroll
                        for (int h = 0; h < 2; ++h) {
                            const int i = 2 * h + c;
                            float t = fmaf(-zv, Xr[mt][h], (float)P[mt][nt][i]);
                            F[mt][nt][i] = fmaf(sv254, t, F[mt][nt][i]);
                        }
                }
            }
        }

        if (s + 1 < NSG) asm volatile("cp.async.wait_group 0;");
        __syncthreads();
        buf ^= 1;
    }

    // ---- output: out = F*Sr + bias ----
    float Sr[2][2];
    #pragma unroll
    for (int mt = 0; mt < 2; ++mt)
        #pragma unroll
        for (int h = 0; h < 2; ++h)
            Sr[mt][h] = smf[OFF_SB / 4 + wm + mt * 16 + r4 + 8 * h];
    #pragma unroll
    for (int mt = 0; mt < 2; ++mt)
        #pragma unroll
        for (int nt = 0; nt < 4; ++nt)
            #pragma unroll
            for (int h = 0; h < 2; ++h) {
                const int row = m0 + wm + mt * 16 + r4 + 8 * h;
                const int cl  = wn + nt * 8 + 2 * kq;
                float2 v;
                v.x = fmaf(F[mt][nt][2 * h + 0], Sr[mt][h], smf[OFF_SB / 4 + 128 + cl]);
                v.y = fmaf(F[mt][nt][2 * h + 1], Sr[mt][h], smf[OFF_SB / 4 + 128 + cl + 1]);
                *(float2*)&out[(size_t)row * T + n0 + cl] = v;
            }
}

extern "C" void kernel_launch(void* const* d_in, const int* in_sizes, int n_in,
                              void* d_out, int out_size)
{
    const float* x      = (const float*)d_in[0];
    const int*   qw     = (const int*)  d_in[1];
    const float* scales = (const float*)d_in[2];
    const float* zeros  = (const float*)d_in[3];
    const float* bias   = (const float*)d_in[4];
    float*       out    = (float*)d_out;

    const int T = in_sizes[4];               // 11008

    quant_kernel<<<MDIM, 128>>>(x);

    cudaFuncSetAttribute(qgemm_i8_kernel,
                         cudaFuncAttributeMaxDynamicSharedMemorySize, SMEMB);
    dim3 grid(T / 128, MDIM / 128);          // 86 x 32
    qgemm_i8_kernel<<<grid, NTH, SMEMB>>>(qw, scales, zeros, bias, out, T);
}